// round 4
// baseline (speedup 1.0000x reference)
#include <cuda_runtime.h>

#define N_NODES 50000
#define N_EDGES 800000
#define F_IN    256
#define HID     128
#define N_CLS   10

// ---------------- scratch (device globals: the sanctioned no-alloc path) ----
__device__ float g_deg[N_NODES];
__device__ float g_dinv[N_NODES];
__device__ int   g_cnt[N_NODES];
__device__ int   g_offs[N_NODES + 1];
__device__ int   g_cur[N_NODES];
__device__ int   g_bsums[128];
__device__ int   g_es[N_EDGES];
__device__ float g_enorm[N_EDGES];
__device__ float g_t[(size_t)N_NODES * HID];   // GEMM output
__device__ float g_a[(size_t)N_NODES * HID];   // aggregated / layer input

// ---------------- degree + CSR build ---------------------------------------
__global__ void k_init() {
    int i = blockIdx.x * blockDim.x + threadIdx.x;
    if (i < N_NODES) { g_deg[i] = 1.0f; g_cnt[i] = 0; }
}

__global__ void k_deg_hist(const int* __restrict__ ei, const float* __restrict__ ew) {
    int e = blockIdx.x * blockDim.x + threadIdx.x;
    if (e < N_EDGES) {
        int d = ei[N_EDGES + e];
        atomicAdd(&g_deg[d], ew[e]);
        atomicAdd(&g_cnt[d], 1);
    }
}

__global__ void k_dinv() {
    int i = blockIdx.x * blockDim.x + threadIdx.x;
    if (i < N_NODES) g_dinv[i] = rsqrtf(g_deg[i]);   // deg >= 1 always (self loop)
}

// block-wise inclusive scan (512), write per-element exclusive partials + block sums
__global__ void k_scan1() {
    __shared__ int sh[512];
    int tid = threadIdx.x;
    int i = blockIdx.x * 512 + tid;
    int v = (i < N_NODES) ? g_cnt[i] : 0;
    sh[tid] = v;
    __syncthreads();
    #pragma unroll
    for (int d = 1; d < 512; d <<= 1) {
        int t = (tid >= d) ? sh[tid - d] : 0;
        __syncthreads();
        sh[tid] += t;
        __syncthreads();
    }
    if (i < N_NODES) g_offs[i] = sh[tid] - v;       // exclusive within block
    if (tid == 511) g_bsums[blockIdx.x] = sh[511];
}

__global__ void k_scan2(int nblocks) {
    __shared__ int sh[128];
    int tid = threadIdx.x;
    int v = (tid < nblocks) ? g_bsums[tid] : 0;
    sh[tid] = v;
    __syncthreads();
    #pragma unroll
    for (int d = 1; d < 128; d <<= 1) {
        int t = (tid >= d) ? sh[tid - d] : 0;
        __syncthreads();
        sh[tid] += t;
        __syncthreads();
    }
    if (tid < nblocks) g_bsums[tid] = sh[tid] - v;  // exclusive block offsets
}

__global__ void k_scan3() {
    int i = blockIdx.x * blockDim.x + threadIdx.x;
    if (i < N_NODES) {
        int o = g_offs[i] + g_bsums[i >> 9];
        g_offs[i] = o;
        g_cur[i]  = o;
    }
    if (i == 0) g_offs[N_NODES] = N_EDGES;
}

__global__ void k_scatter(const int* __restrict__ ei, const float* __restrict__ ew) {
    int e = blockIdx.x * blockDim.x + threadIdx.x;
    if (e < N_EDGES) {
        int s = ei[e];
        int d = ei[N_EDGES + e];
        int p = atomicAdd(&g_cur[d], 1);
        g_es[p]    = s;
        g_enorm[p] = g_dinv[s] * ew[e] * g_dinv[d];
    }
}

// ---------------- SGEMM: g_t[M x 128] = A[M x K] * B[K x 128] --------------
// use_internal != 0 -> A = g_a (device symbol), else A = Aext.
// Double-buffered SMEM (ping-pong): one barrier per K-slab; STS of slab k+1
// overlaps FMA block of slab k.
__global__ __launch_bounds__(256, 2)
void k_sgemm(const float* __restrict__ Aext, const float* __restrict__ B,
             int use_internal, int M, int K) {
    const float* __restrict__ A = use_internal ? g_a : Aext;
    __shared__ float As[2][8][128];
    __shared__ float Bs[2][8][128];
    const int tid = threadIdx.x;
    const int block_row = blockIdx.x * 128;
    const int a_row = tid >> 1;
    const int a_k   = (tid & 1) * 4;
    const int b_k   = tid >> 5;
    const int b_col = (tid & 31) * 4;
    const int tr = tid >> 4;
    const int tc = tid & 15;

    float acc[8][8];
    #pragma unroll
    for (int i = 0; i < 8; i++)
        #pragma unroll
        for (int j = 0; j < 8; j++) acc[i][j] = 0.0f;

    const int  grow = block_row + a_row;
    const bool arow_ok = grow < M;
    const float* a_ptr = A + (size_t)grow * K + a_k;
    const float* b_ptr = B + (size_t)b_k * HID + b_col;

    // prologue: fill buffer 0 with slab 0
    {
        float4 av = arow_ok ? *(const float4*)(a_ptr)
                            : make_float4(0.f, 0.f, 0.f, 0.f);
        float4 bv = *(const float4*)(b_ptr);
        As[0][a_k + 0][a_row] = av.x;
        As[0][a_k + 1][a_row] = av.y;
        As[0][a_k + 2][a_row] = av.z;
        As[0][a_k + 3][a_row] = av.w;
        *(float4*)&Bs[0][b_k][b_col] = bv;
    }
    __syncthreads();

    int cur = 0;
    for (int k0 = 0; k0 < K; k0 += 8) {
        const bool has_next = (k0 + 8 < K);
        float4 av, bv;
        if (has_next) {
            av = arow_ok ? *(const float4*)(a_ptr + k0 + 8)
                         : make_float4(0.f, 0.f, 0.f, 0.f);
            bv = *(const float4*)(b_ptr + (size_t)(k0 + 8) * HID);
        }

        #pragma unroll
        for (int k = 0; k < 8; k++) {
            float ra[8], rb[8];
            #pragma unroll
            for (int i = 0; i < 8; i++) ra[i] = As[cur][k][tr * 8 + i];
            #pragma unroll
            for (int j = 0; j < 8; j++) rb[j] = Bs[cur][k][tc * 8 + j];
            #pragma unroll
            for (int i = 0; i < 8; i++)
                #pragma unroll
                for (int j = 0; j < 8; j++) acc[i][j] += ra[i] * rb[j];
        }

        if (has_next) {
            int nxt = cur ^ 1;
            As[nxt][a_k + 0][a_row] = av.x;
            As[nxt][a_k + 1][a_row] = av.y;
            As[nxt][a_k + 2][a_row] = av.z;
            As[nxt][a_k + 3][a_row] = av.w;
            *(float4*)&Bs[nxt][b_k][b_col] = bv;
            __syncthreads();
            cur = nxt;
        }
    }

    #pragma unroll
    for (int i = 0; i < 8; i++) {
        int row = block_row + tr * 8 + i;
        if (row < M) {
            float4 v0 = make_float4(acc[i][0], acc[i][1], acc[i][2], acc[i][3]);
            float4 v1 = make_float4(acc[i][4], acc[i][5], acc[i][6], acc[i][7]);
            *(float4*)(g_t + (size_t)row * HID + tc * 8)     = v0;
            *(float4*)(g_t + (size_t)row * HID + tc * 8 + 4) = v1;
        }
    }
}

// ---------------- pull aggregation + bias + ReLU (warp per node) -----------
// reads g_t, writes g_a.  8-deep gather unroll -> MLP ~8 to cover L2 latency.
__global__ void k_agg(const float* __restrict__ bias) {
    int gw   = (blockIdx.x * blockDim.x + threadIdx.x) >> 5;
    int lane = threadIdx.x & 31;
    if (gw >= N_NODES) return;
    const float* __restrict__ t = g_t;

    float di = g_dinv[gw];
    float sw = di * di;                                   // self-loop weight
    float4 v = *(const float4*)(t + (size_t)gw * HID + lane * 4);
    float ax = sw * v.x, ay = sw * v.y, az = sw * v.z, aw = sw * v.w;

    int beg = g_offs[gw], end = g_offs[gw + 1];
    int j = beg;
    for (; j + 8 <= end; j += 8) {
        int s[8]; float w[8]; float4 vv[8];
        #pragma unroll
        for (int u = 0; u < 8; u++) { s[u] = g_es[j + u]; w[u] = g_enorm[j + u]; }
        #pragma unroll
        for (int u = 0; u < 8; u++)
            vv[u] = *(const float4*)(t + (size_t)s[u] * HID + lane * 4);
        #pragma unroll
        for (int u = 0; u < 8; u++) {
            ax += w[u] * vv[u].x;
            ay += w[u] * vv[u].y;
            az += w[u] * vv[u].z;
            aw += w[u] * vv[u].w;
        }
    }
    for (; j < end; j++) {
        int s = g_es[j]; float w = g_enorm[j];
        float4 vv = *(const float4*)(t + (size_t)s * HID + lane * 4);
        ax += w * vv.x; ay += w * vv.y; az += w * vv.z; aw += w * vv.w;
    }

    float4 bb = *(const float4*)(bias + lane * 4);
    ax = fmaxf(ax + bb.x, 0.f);
    ay = fmaxf(ay + bb.y, 0.f);
    az = fmaxf(az + bb.z, 0.f);
    aw = fmaxf(aw + bb.w, 0.f);
    *(float4*)(g_a + (size_t)gw * HID + lane * 4) = make_float4(ax, ay, az, aw);
}

// ---------------- final FC + softmax (thread per node) ---------------------
__global__ void k_fc(const float* __restrict__ fcw, const float* __restrict__ fcb,
                     float* __restrict__ out) {
    __shared__ float sw[HID * N_CLS];
    for (int i = threadIdx.x; i < HID * N_CLS; i += blockDim.x) sw[i] = fcw[i];
    __syncthreads();
    int n = blockIdx.x * blockDim.x + threadIdx.x;
    if (n >= N_NODES) return;

    float acc[N_CLS];
    #pragma unroll
    for (int c = 0; c < N_CLS; c++) acc[c] = fcb[c];

    const float4* hr = (const float4*)(g_a + (size_t)n * HID);
    #pragma unroll 4
    for (int f4 = 0; f4 < HID / 4; f4++) {
        float4 hv = hr[f4];
        int fb = f4 * 4;
        #pragma unroll
        for (int c = 0; c < N_CLS; c++) {
            acc[c] += hv.x * sw[(fb + 0) * N_CLS + c];
            acc[c] += hv.y * sw[(fb + 1) * N_CLS + c];
            acc[c] += hv.z * sw[(fb + 2) * N_CLS + c];
            acc[c] += hv.w * sw[(fb + 3) * N_CLS + c];
        }
    }
    float m = acc[0];
    #pragma unroll
    for (int c = 1; c < N_CLS; c++) m = fmaxf(m, acc[c]);
    float s = 0.f;
    #pragma unroll
    for (int c = 0; c < N_CLS; c++) { acc[c] = expf(acc[c] - m); s += acc[c]; }
    float inv = 1.f / s;
    #pragma unroll
    for (int c = 0; c < N_CLS; c++) out[(size_t)n * N_CLS + c] = acc[c] * inv;
}

// ---------------- host ------------------------------------------------------
extern "C" void kernel_launch(void* const* d_in, const int* in_sizes, int n_in,
                              void* d_out, int out_size) {
    const float* x   = (const float*)d_in[0];
    const int*   ei  = (const int*)  d_in[1];
    const float* ew  = (const float*)d_in[2];
    const float* W1  = (const float*)d_in[3];
    const float* b1  = (const float*)d_in[4];
    const float* W2  = (const float*)d_in[5];
    const float* b2  = (const float*)d_in[6];
    const float* W3  = (const float*)d_in[7];
    const float* b3  = (const float*)d_in[8];
    const float* fcw = (const float*)d_in[9];
    const float* fcb = (const float*)d_in[10];
    float* out = (float*)d_out;

    const int NB_N   = (N_NODES + 255) / 256;
    const int NB_E   = (N_EDGES + 255) / 256;
    const int NB_S1  = (N_NODES + 511) / 512;          // 98
    const int NB_GM  = (N_NODES + 127) / 128;          // 391
    const int NB_AGG = (N_NODES * 32 + 255) / 256;     // 6250

    // degree + CSR build (per launch, fully capturable)
    k_init<<<NB_N, 256>>>();
    k_deg_hist<<<NB_E, 256>>>(ei, ew);
    k_dinv<<<NB_N, 256>>>();
    k_scan1<<<NB_S1, 512>>>();
    k_scan2<<<1, 128>>>(NB_S1);
    k_scan3<<<NB_N, 256>>>();
    k_scatter<<<NB_E, 256>>>(ei, ew);

    // layer 1: t = x @ W1 ; a = relu(agg(t) + b1)
    k_sgemm<<<NB_GM, 256>>>(x, W1, 0, N_NODES, F_IN);
    k_agg<<<NB_AGG, 256>>>(b1);
    // layer 2
    k_sgemm<<<NB_GM, 256>>>(nullptr, W2, 1, N_NODES, HID);
    k_agg<<<NB_AGG, 256>>>(b2);
    // layer 3
    k_sgemm<<<NB_GM, 256>>>(nullptr, W3, 1, N_NODES, HID);
    k_agg<<<NB_AGG, 256>>>(b3);

    // classifier + softmax
    k_fc<<<NB_N, 256>>>(fcw, fcb, out);
}

// round 11
// speedup vs baseline: 1.3223x; 1.3223x over previous
#include <cuda_runtime.h>
#include <cuda_bf16.h>

#define N_NODES 50000
#define N_EDGES 800000
#define F_IN    256
#define HID     128
#define N_CLS   10
#define WSLOT   (HID * F_IN)   // 32768: per-layer transposed-weight slot

// ---------------- scratch (device globals: the sanctioned no-alloc path) ----
__device__ float g_deg[N_NODES];
__device__ float g_dinv[N_NODES];
__device__ int   g_cnt[N_NODES];
__device__ int   g_offs[N_NODES + 1];
__device__ int   g_cur[N_NODES];
__device__ int   g_bsums[128];
__device__ int   g_es[N_EDGES];
__device__ float g_enorm[N_EDGES];
__device__ float g_t[(size_t)N_NODES * HID];   // GEMM output (fp32)
__device__ float g_a[(size_t)N_NODES * HID];   // aggregated / layer input (fp32)
// split-bf16 operands for tensor-core GEMM
__device__ __nv_bfloat16 g_xhi[(size_t)N_NODES * F_IN];
__device__ __nv_bfloat16 g_xlo[(size_t)N_NODES * F_IN];
__device__ __nv_bfloat16 g_ahi[(size_t)N_NODES * HID];
__device__ __nv_bfloat16 g_alo[(size_t)N_NODES * HID];
__device__ __nv_bfloat16 g_wth[3 * WSLOT];     // W^T hi, [n][k], per layer slot
__device__ __nv_bfloat16 g_wtl[3 * WSLOT];     // W^T lo

// ---------------- helpers ---------------------------------------------------
__device__ __forceinline__ void bf16_split(float x, __nv_bfloat16& h, __nv_bfloat16& l) {
    h = __float2bfloat16(x);
    l = __float2bfloat16(x - __bfloat162float(h));
}
__device__ __forceinline__ unsigned pk2(__nv_bfloat16 a, __nv_bfloat16 b) {
    return (unsigned)__bfloat16_as_ushort(a) | ((unsigned)__bfloat16_as_ushort(b) << 16);
}

#define MMA_BF16(d, A0, A1, A2, A3, B0, B1)                                  \
    asm volatile("mma.sync.aligned.m16n8k16.row.col.f32.bf16.bf16.f32 "      \
                 "{%0,%1,%2,%3}, {%4,%5,%6,%7}, {%8,%9}, {%0,%1,%2,%3};\n"   \
                 : "+f"(d[0]), "+f"(d[1]), "+f"(d[2]), "+f"(d[3])            \
                 : "r"(A0), "r"(A1), "r"(A2), "r"(A3), "r"(B0), "r"(B1))

// ---------------- degree + CSR build ---------------------------------------
__global__ void k_init() {
    int i = blockIdx.x * blockDim.x + threadIdx.x;
    if (i < N_NODES) { g_deg[i] = 1.0f; g_cnt[i] = 0; }
}

__global__ void k_deg_hist(const int* __restrict__ ei, const float* __restrict__ ew) {
    int e = blockIdx.x * blockDim.x + threadIdx.x;
    if (e < N_EDGES) {
        int d = ei[N_EDGES + e];
        atomicAdd(&g_deg[d], ew[e]);
        atomicAdd(&g_cnt[d], 1);
    }
}

__global__ void k_dinv() {
    int i = blockIdx.x * blockDim.x + threadIdx.x;
    if (i < N_NODES) g_dinv[i] = rsqrtf(g_deg[i]);   // deg >= 1 always (self loop)
}

__global__ void k_scan1() {
    __shared__ int sh[512];
    int tid = threadIdx.x;
    int i = blockIdx.x * 512 + tid;
    int v = (i < N_NODES) ? g_cnt[i] : 0;
    sh[tid] = v;
    __syncthreads();
    #pragma unroll
    for (int d = 1; d < 512; d <<= 1) {
        int t = (tid >= d) ? sh[tid - d] : 0;
        __syncthreads();
        sh[tid] += t;
        __syncthreads();
    }
    if (i < N_NODES) g_offs[i] = sh[tid] - v;
    if (tid == 511) g_bsums[blockIdx.x] = sh[511];
}

__global__ void k_scan2(int nblocks) {
    __shared__ int sh[128];
    int tid = threadIdx.x;
    int v = (tid < nblocks) ? g_bsums[tid] : 0;
    sh[tid] = v;
    __syncthreads();
    #pragma unroll
    for (int d = 1; d < 128; d <<= 1) {
        int t = (tid >= d) ? sh[tid - d] : 0;
        __syncthreads();
        sh[tid] += t;
        __syncthreads();
    }
    if (tid < nblocks) g_bsums[tid] = sh[tid] - v;
}

__global__ void k_scan3() {
    int i = blockIdx.x * blockDim.x + threadIdx.x;
    if (i < N_NODES) {
        int o = g_offs[i] + g_bsums[i >> 9];
        g_offs[i] = o;
        g_cur[i]  = o;
    }
    if (i == 0) g_offs[N_NODES] = N_EDGES;
}

__global__ void k_scatter(const int* __restrict__ ei, const float* __restrict__ ew) {
    int e = blockIdx.x * blockDim.x + threadIdx.x;
    if (e < N_EDGES) {
        int s = ei[e];
        int d = ei[N_EDGES + e];
        int p = atomicAdd(&g_cur[d], 1);
        g_es[p]    = s;
        g_enorm[p] = g_dinv[s] * ew[e] * g_dinv[d];
    }
}

// ---------------- bf16-split conversions ------------------------------------
__global__ void k_cvt_x(const float* __restrict__ x) {
    int i = blockIdx.x * blockDim.x + threadIdx.x;
    if (i >= N_NODES * F_IN / 4) return;
    float4 v = ((const float4*)x)[i];
    __nv_bfloat16 h0, l0, h1, l1, h2, l2, h3, l3;
    bf16_split(v.x, h0, l0); bf16_split(v.y, h1, l1);
    bf16_split(v.z, h2, l2); bf16_split(v.w, h3, l3);
    *(uint2*)&g_xhi[(size_t)i * 4] = make_uint2(pk2(h0, h1), pk2(h2, h3));
    *(uint2*)&g_xlo[(size_t)i * 4] = make_uint2(pk2(l0, l1), pk2(l2, l3));
}

// W [K,HID] row-major -> W^T [n][k] bf16 hi/lo into slot widx
__global__ void k_cvt_w(const float* __restrict__ W, int K, int widx) {
    int id = blockIdx.x * blockDim.x + threadIdx.x;
    if (id >= HID * K) return;
    int n = id / K, k = id % K;
    float w = W[(size_t)k * HID + n];
    __nv_bfloat16 h, l;
    bf16_split(w, h, l);
    g_wth[(size_t)widx * WSLOT + id] = h;
    g_wtl[(size_t)widx * WSLOT + id] = l;
}

// ---------------- tensor-core GEMM: g_t[M x 128] = A[M x K] * W[K x 128] ----
// A = split-bf16 (xhi/xlo if src_sel==0 else ahi/alo), W^T = g_wth/g_wtl slot.
// 3-term split: hi*Whi + hi*Wlo + lo*Whi, fp32 accumulate (error ~2^-16/term).
// CTA 128x128, 8 warps (2x4), warp tile 64x32 = 4x4 m16n8k16 atoms.
// K-slab 16, double-buffered smem, padded rows (24 bf16) -> conflict-free LDS.
__global__ __launch_bounds__(256)
void k_gemm_bf16(int src_sel, int widx, int K) {
    const __nv_bfloat16* __restrict__ Ah = src_sel ? g_ahi : g_xhi;
    const __nv_bfloat16* __restrict__ Al = src_sel ? g_alo : g_xlo;
    const __nv_bfloat16* __restrict__ Bh = g_wth + (size_t)widx * WSLOT;
    const __nv_bfloat16* __restrict__ Bl = g_wtl + (size_t)widx * WSLOT;

    __shared__ __nv_bfloat16 sAh[2][128][24];
    __shared__ __nv_bfloat16 sAl[2][128][24];
    __shared__ __nv_bfloat16 sBh[2][128][24];
    __shared__ __nv_bfloat16 sBl[2][128][24];

    const int tid  = threadIdx.x;
    const int lane = tid & 31;
    const int wid  = tid >> 5;
    const int wm   = wid >> 2;            // 0..1 (64-row halves)
    const int wn   = wid & 3;             // 0..3 (32-col quarters)
    const int block_row = blockIdx.x * 128;

    // global->smem mapping: thread loads one uint4 (8 bf16) per array per slab
    const int lrow = tid >> 1;            // 0..127
    const int lk   = (tid & 1) * 8;       // 0 or 8
    const int arow = block_row + lrow;
    const bool aok = arow < N_NODES;

    float acc[4][4][4];
    #pragma unroll
    for (int i = 0; i < 4; i++)
        #pragma unroll
        for (int j = 0; j < 4; j++)
            #pragma unroll
            for (int q = 0; q < 4; q++) acc[i][j][q] = 0.0f;

    const uint4 z4 = make_uint4(0, 0, 0, 0);
    uint4 va_h, va_l, vb_h, vb_l;

    // prologue: slab 0 -> buffer 0
    {
        size_t ao = (size_t)arow * K + lk;
        size_t bo = (size_t)lrow * K + lk;
        va_h = aok ? *(const uint4*)(Ah + ao) : z4;
        va_l = aok ? *(const uint4*)(Al + ao) : z4;
        vb_h = *(const uint4*)(Bh + bo);
        vb_l = *(const uint4*)(Bl + bo);
        *(uint4*)&sAh[0][lrow][lk] = va_h;
        *(uint4*)&sAl[0][lrow][lk] = va_l;
        *(uint4*)&sBh[0][lrow][lk] = vb_h;
        *(uint4*)&sBl[0][lrow][lk] = vb_l;
    }
    __syncthreads();

    const int gid = lane >> 2;            // 0..7
    const int kp  = (lane & 3) * 2;       // 0,2,4,6

    int cur = 0;
    for (int k0 = 0; k0 < K; k0 += 16) {
        const bool has_next = (k0 + 16) < K;
        if (has_next) {
            size_t ao = (size_t)arow * K + k0 + 16 + lk;
            size_t bo = (size_t)lrow * K + k0 + 16 + lk;
            va_h = aok ? *(const uint4*)(Ah + ao) : z4;
            va_l = aok ? *(const uint4*)(Al + ao) : z4;
            vb_h = *(const uint4*)(Bh + bo);
            vb_l = *(const uint4*)(Bl + bo);
        }

        unsigned ah[4][4], al[4][4], bh[4][2], bl[4][2];
        #pragma unroll
        for (int ma = 0; ma < 4; ma++) {
            int r = wm * 64 + ma * 16 + gid;
            ah[ma][0] = *(const unsigned*)&sAh[cur][r][kp];
            ah[ma][1] = *(const unsigned*)&sAh[cur][r + 8][kp];
            ah[ma][2] = *(const unsigned*)&sAh[cur][r][kp + 8];
            ah[ma][3] = *(const unsigned*)&sAh[cur][r + 8][kp + 8];
            al[ma][0] = *(const unsigned*)&sAl[cur][r][kp];
            al[ma][1] = *(const unsigned*)&sAl[cur][r + 8][kp];
            al[ma][2] = *(const unsigned*)&sAl[cur][r][kp + 8];
            al[ma][3] = *(const unsigned*)&sAl[cur][r + 8][kp + 8];
        }
        #pragma unroll
        for (int na = 0; na < 4; na++) {
            int n = wn * 32 + na * 8 + gid;
            bh[na][0] = *(const unsigned*)&sBh[cur][n][kp];
            bh[na][1] = *(const unsigned*)&sBh[cur][n][kp + 8];
            bl[na][0] = *(const unsigned*)&sBl[cur][n][kp];
            bl[na][1] = *(const unsigned*)&sBl[cur][n][kp + 8];
        }

        #pragma unroll
        for (int ma = 0; ma < 4; ma++)
            #pragma unroll
            for (int na = 0; na < 4; na++) {
                MMA_BF16(acc[ma][na], ah[ma][0], ah[ma][1], ah[ma][2], ah[ma][3],
                         bh[na][0], bh[na][1]);
                MMA_BF16(acc[ma][na], ah[ma][0], ah[ma][1], ah[ma][2], ah[ma][3],
                         bl[na][0], bl[na][1]);
                MMA_BF16(acc[ma][na], al[ma][0], al[ma][1], al[ma][2], al[ma][3],
                         bh[na][0], bh[na][1]);
            }

        if (has_next) {
            int nxt = cur ^ 1;
            *(uint4*)&sAh[nxt][lrow][lk] = va_h;
            *(uint4*)&sAl[nxt][lrow][lk] = va_l;
            *(uint4*)&sBh[nxt][lrow][lk] = vb_h;
            *(uint4*)&sBl[nxt][lrow][lk] = vb_l;
            __syncthreads();
            cur = nxt;
        }
    }

    // epilogue: fp32 accumulators -> g_t
    #pragma unroll
    for (int ma = 0; ma < 4; ma++) {
        int gr = block_row + wm * 64 + ma * 16 + gid;
        #pragma unroll
        for (int na = 0; na < 4; na++) {
            int gc = wn * 32 + na * 8 + (lane & 3) * 2;
            if (gr < N_NODES)
                *(float2*)&g_t[(size_t)gr * HID + gc] =
                    make_float2(acc[ma][na][0], acc[ma][na][1]);
            if (gr + 8 < N_NODES)
                *(float2*)&g_t[(size_t)(gr + 8) * HID + gc] =
                    make_float2(acc[ma][na][2], acc[ma][na][3]);
        }
    }
}

// ---------------- pull aggregation + bias + ReLU (warp per node) -----------
// reads g_t, writes g_a (fp32) AND g_ahi/g_alo (split-bf16 for next GEMM).
__global__ void k_agg(const float* __restrict__ bias) {
    int gw   = (blockIdx.x * blockDim.x + threadIdx.x) >> 5;
    int lane = threadIdx.x & 31;
    if (gw >= N_NODES) return;
    const float* __restrict__ t = g_t;

    float di = g_dinv[gw];
    float sw = di * di;                                   // self-loop weight
    float4 v = *(const float4*)(t + (size_t)gw * HID + lane * 4);
    float ax = sw * v.x, ay = sw * v.y, az = sw * v.z, aw = sw * v.w;

    int beg = g_offs[gw], end = g_offs[gw + 1];
    int j = beg;
    for (; j + 8 <= end; j += 8) {
        int s[8]; float w[8]; float4 vv[8];
        #pragma unroll
        for (int u = 0; u < 8; u++) { s[u] = g_es[j + u]; w[u] = g_enorm[j + u]; }
        #pragma unroll
        for (int u = 0; u < 8; u++)
            vv[u] = *(const float4*)(t + (size_t)s[u] * HID + lane * 4);
        #pragma unroll
        for (int u = 0; u < 8; u++) {
            ax += w[u] * vv[u].x;
            ay += w[u] * vv[u].y;
            az += w[u] * vv[u].z;
            aw += w[u] * vv[u].w;
        }
    }
    for (; j < end; j++) {
        int s = g_es[j]; float w = g_enorm[j];
        float4 vv = *(const float4*)(t + (size_t)s * HID + lane * 4);
        ax += w * vv.x; ay += w * vv.y; az += w * vv.z; aw += w * vv.w;
    }

    float4 bb = *(const float4*)(bias + lane * 4);
    ax = fmaxf(ax + bb.x, 0.f);
    ay = fmaxf(ay + bb.y, 0.f);
    az = fmaxf(az + bb.z, 0.f);
    aw = fmaxf(aw + bb.w, 0.f);

    size_t o = (size_t)gw * HID + lane * 4;
    *(float4*)(g_a + o) = make_float4(ax, ay, az, aw);

    __nv_bfloat16 h0, l0, h1, l1, h2, l2, h3, l3;
    bf16_split(ax, h0, l0); bf16_split(ay, h1, l1);
    bf16_split(az, h2, l2); bf16_split(aw, h3, l3);
    *(uint2*)(g_ahi + o) = make_uint2(pk2(h0, h1), pk2(h2, h3));
    *(uint2*)(g_alo + o) = make_uint2(pk2(l0, l1), pk2(l2, l3));
}

// ---------------- final FC + softmax (thread per node) ---------------------
__global__ void k_fc(const float* __restrict__ fcw, const float* __restrict__ fcb,
                     float* __restrict__ out) {
    __shared__ float sw[HID * N_CLS];
    for (int i = threadIdx.x; i < HID * N_CLS; i += blockDim.x) sw[i] = fcw[i];
    __syncthreads();
    int n = blockIdx.x * blockDim.x + threadIdx.x;
    if (n >= N_NODES) return;

    float acc[N_CLS];
    #pragma unroll
    for (int c = 0; c < N_CLS; c++) acc[c] = fcb[c];

    const float4* hr = (const float4*)(g_a + (size_t)n * HID);
    #pragma unroll 4
    for (int f4 = 0; f4 < HID / 4; f4++) {
        float4 hv = hr[f4];
        int fb = f4 * 4;
        #pragma unroll
        for (int c = 0; c < N_CLS; c++) {
            acc[c] += hv.x * sw[(fb + 0) * N_CLS + c];
            acc[c] += hv.y * sw[(fb + 1) * N_CLS + c];
            acc[c] += hv.z * sw[(fb + 2) * N_CLS + c];
            acc[c] += hv.w * sw[(fb + 3) * N_CLS + c];
        }
    }
    float m = acc[0];
    #pragma unroll
    for (int c = 1; c < N_CLS; c++) m = fmaxf(m, acc[c]);
    float s = 0.f;
    #pragma unroll
    for (int c = 0; c < N_CLS; c++) { acc[c] = expf(acc[c] - m); s += acc[c]; }
    float inv = 1.f / s;
    #pragma unroll
    for (int c = 0; c < N_CLS; c++) out[(size_t)n * N_CLS + c] = acc[c] * inv;
}

// ---------------- host ------------------------------------------------------
extern "C" void kernel_launch(void* const* d_in, const int* in_sizes, int n_in,
                              void* d_out, int out_size) {
    const float* x   = (const float*)d_in[0];
    const int*   ei  = (const int*)  d_in[1];
    const float* ew  = (const float*)d_in[2];
    const float* W1  = (const float*)d_in[3];
    const float* b1  = (const float*)d_in[4];
    const float* W2  = (const float*)d_in[5];
    const float* b2  = (const float*)d_in[6];
    const float* W3  = (const float*)d_in[7];
    const float* b3  = (const float*)d_in[8];
    const float* fcw = (const float*)d_in[9];
    const float* fcb = (const float*)d_in[10];
    float* out = (float*)d_out;

    const int NB_N   = (N_NODES + 255) / 256;
    const int NB_E   = (N_EDGES + 255) / 256;
    const int NB_S1  = (N_NODES + 511) / 512;          // 98
    const int NB_GM  = (N_NODES + 127) / 128;          // 391
    const int NB_AGG = (N_NODES * 32 + 255) / 256;     // 6250
    const int NB_CVX = (N_NODES * F_IN / 4 + 255) / 256;

    // operand conversions (independent of CSR build; same stream = ordered)
    k_cvt_x<<<NB_CVX, 256>>>(x);
    k_cvt_w<<<(HID * F_IN + 255) / 256, 256>>>(W1, F_IN, 0);
    k_cvt_w<<<(HID * HID + 255) / 256, 256>>>(W2, HID, 1);
    k_cvt_w<<<(HID * HID + 255) / 256, 256>>>(W3, HID, 2);

    // degree + CSR build (per launch, fully capturable)
    k_init<<<NB_N, 256>>>();
    k_deg_hist<<<NB_E, 256>>>(ei, ew);
    k_dinv<<<NB_N, 256>>>();
    k_scan1<<<NB_S1, 512>>>();
    k_scan2<<<1, 128>>>(NB_S1);
    k_scan3<<<NB_N, 256>>>();
    k_scatter<<<NB_E, 256>>>(ei, ew);

    // layer 1: t = x @ W1 ; a = relu(agg(t) + b1)
    k_gemm_bf16<<<NB_GM, 256>>>(0, 0, F_IN);
    k_agg<<<NB_AGG, 256>>>(b1);
    // layer 2
    k_gemm_bf16<<<NB_GM, 256>>>(1, 1, HID);
    k_agg<<<NB_AGG, 256>>>(b2);
    // layer 3
    k_gemm_bf16<<<NB_GM, 256>>>(1, 2, HID);
    k_agg<<<NB_AGG, 256>>>(b3);

    // classifier + softmax
    k_fc<<<NB_N, 256>>>(fcw, fcb, out);
}